// round 6
// baseline (speedup 1.0000x reference)
#include <cuda_runtime.h>
#include <cuda_bf16.h>
#include <stdint.h>
#include <math.h>

// Shapes (fixed): B=4, S=2, T=1024, D=512, H=8, HD=64, M = B*S*T = 8192
// bf16 tensor-core GEMMs (mma.sync m16n8k16, fp32 accum).
// Scores kernel stores p=exp(logit) (no max subtraction; logits O(1)) + partial
// row sums; fused AV kernel normalizes + competitive-combines inline.

// ---------------- device workspaces ----------------
__device__ __nv_bfloat16 g_Xh[8192ull * 512];
__device__ __nv_bfloat16 g_Wh[4ull * 512 * 512];  // [Wq;Wk;Wv;Wo]
__device__ __nv_bfloat16 g_Qh[8192ull * 512];     // Q*0.125 (scale folded)
__device__ __nv_bfloat16 g_Kh[8192ull * 512];
__device__ __nv_bfloat16 g_Vh[8192ull * 512];
__device__ __nv_bfloat16 g_S[67108864ull];        // [ss][bh][q][k] unnormalized probs
__device__ float         g_zpart[524288];         // [ss][bh][nblk(8)][q]  partial row sums
__device__ __nv_bfloat16 g_attnh[8192ull * 512];
__device__ float         g_proj[8192ull * 512];

// ---------------- helpers ----------------
__device__ __forceinline__ uint32_t pack_bf16x2(float a, float b) {
    __nv_bfloat162 h = __floats2bfloat162_rn(a, b);
    return *reinterpret_cast<uint32_t*>(&h);
}

__device__ __forceinline__ void mma16816(float* c, const uint32_t* a, uint32_t b0, uint32_t b1) {
    asm volatile(
        "mma.sync.aligned.m16n8k16.row.col.f32.bf16.bf16.f32 "
        "{%0,%1,%2,%3}, {%4,%5,%6,%7}, {%8,%9}, {%0,%1,%2,%3};\n"
        : "+f"(c[0]), "+f"(c[1]), "+f"(c[2]), "+f"(c[3])
        : "r"(a[0]), "r"(a[1]), "r"(a[2]), "r"(a[3]), "r"(b0), "r"(b1));
}

__device__ __forceinline__ float blk_red_sum(float v, float* sm) {
    int lane = threadIdx.x & 31, wid = threadIdx.x >> 5;
#pragma unroll
    for (int o = 16; o; o >>= 1) v += __shfl_xor_sync(0xffffffffu, v, o);
    if (lane == 0) sm[wid] = v;
    __syncthreads();
    float r = 0.f;
#pragma unroll
    for (int i = 0; i < 8; i++) r += sm[i];
    __syncthreads();
    return r;
}

// ---------------- 0) convert inputs to bf16 ----------------
__global__ __launch_bounds__(256) void k_prep(
    const float* __restrict__ X,
    const float* __restrict__ Wq, const float* __restrict__ Wk,
    const float* __restrict__ Wv, const float* __restrict__ Wo)
{
    const int idx = blockIdx.x * 256 + threadIdx.x;
    if (idx < 1048576) {
        float4 v = ((const float4*)X)[idx];
        uint2 o; o.x = pack_bf16x2(v.x, v.y); o.y = pack_bf16x2(v.z, v.w);
        ((uint2*)g_Xh)[idx] = o;
    } else {
        int j = idx - 1048576;
        int w = j >> 16;
        const float4* src = (w == 0) ? (const float4*)Wq : (w == 1) ? (const float4*)Wk
                          : (w == 2) ? (const float4*)Wv : (const float4*)Wo;
        float4 v = src[j & 65535];
        uint2 o; o.x = pack_bf16x2(v.x, v.y); o.y = pack_bf16x2(v.z, v.w);
        ((uint2*)g_Wh)[j] = o;
    }
}

// ---------------- 1) QKV projection (bf16 mma) ----------------
__global__ __launch_bounds__(128) void k_qkv_mma(
    const float* __restrict__ bq, const float* __restrict__ bk, const float* __restrict__ bv)
{
    __shared__ __nv_bfloat16 As[128][40];
    __shared__ __nv_bfloat16 Bs[128][40];
    const int tid = threadIdx.x, lane = tid & 31, warp = tid >> 5;
    const int wm = warp >> 1, wn = warp & 1;
    const int g = lane >> 2, t = lane & 3;
    const int m0 = blockIdx.y * 128, n0g = blockIdx.x * 128;

    float acc[4][8][4] = {};

    for (int k0 = 0; k0 < 512; k0 += 32) {
        {
            const __nv_bfloat16* srcA = g_Xh + (size_t)(m0 + tid) * 512 + k0;
            const __nv_bfloat16* srcB = g_Wh + (size_t)(n0g + tid) * 512 + k0;
#pragma unroll
            for (int c = 0; c < 4; c++) {
                *(uint4*)&As[tid][c * 8] = *(const uint4*)(srcA + c * 8);
                *(uint4*)&Bs[tid][c * 8] = *(const uint4*)(srcB + c * 8);
            }
        }
        __syncthreads();
#pragma unroll
        for (int kk = 0; kk < 32; kk += 16) {
            uint32_t a[4][4];
#pragma unroll
            for (int mi = 0; mi < 4; mi++)
#pragma unroll
                for (int p = 0; p < 4; p++)
                    a[mi][p] = *(const uint32_t*)&As[wm * 64 + mi * 16 + ((p & 1) << 3) + g]
                                                   [kk + 2 * t + ((p >> 1) << 3)];
#pragma unroll
            for (int ni = 0; ni < 8; ni++) {
                uint32_t b0 = *(const uint32_t*)&Bs[wn * 64 + ni * 8 + g][kk + 2 * t];
                uint32_t b1 = *(const uint32_t*)&Bs[wn * 64 + ni * 8 + g][kk + 2 * t + 8];
#pragma unroll
                for (int mi = 0; mi < 4; mi++) mma16816(acc[mi][ni], a[mi], b0, b1);
            }
        }
        __syncthreads();
    }

    const int mat = n0g >> 9, nloc = n0g & 511;
    const float* bias = (mat == 0) ? bq : (mat == 1) ? bk : bv;
    __nv_bfloat16* out = (mat == 0) ? g_Qh : (mat == 1) ? g_Kh : g_Vh;
    const float scale = (mat == 0) ? 0.125f : 1.0f;

#pragma unroll
    for (int mi = 0; mi < 4; mi++) {
        int r0 = m0 + wm * 64 + mi * 16 + g;
#pragma unroll
        for (int ni = 0; ni < 8; ni++) {
            int col = nloc + wn * 64 + ni * 8 + 2 * t;
            float b0f = bias[col], b1f = bias[col + 1];
            *(uint32_t*)(out + (size_t)r0 * 512 + col) =
                pack_bf16x2((acc[mi][ni][0] + b0f) * scale, (acc[mi][ni][1] + b1f) * scale);
            *(uint32_t*)(out + (size_t)(r0 + 8) * 512 + col) =
                pack_bf16x2((acc[mi][ni][2] + b0f) * scale, (acc[mi][ni][3] + b1f) * scale);
        }
    }
}

// ---------------- 2) scores: p = exp(Qs_ss @ K_{1-ss}^T), + partial row sums ----
// grid (8, 8, 64): x = nblk, y = mblk, z = ss*32 + b*8 + h.
__global__ __launch_bounds__(128) void k_scores_mma()
{
    __shared__ __nv_bfloat16 As[128][40];
    __shared__ __nv_bfloat16 Bs[128][40];
    __shared__ float zs[128][2];
    const int z = blockIdx.z;
    const int ss = z >> 5, bh = z & 31, b = bh >> 3, h = bh & 7;
    const __nv_bfloat16* Abase = g_Qh + ((size_t)(b * 2 + ss) * 1024) * 512 + h * 64;
    const __nv_bfloat16* Bbase = g_Kh + ((size_t)(b * 2 + (1 - ss)) * 1024) * 512 + h * 64;
    __nv_bfloat16* C = g_S + ((size_t)z << 20);

    const int tid = threadIdx.x, lane = tid & 31, warp = tid >> 5;
    const int wm = warp >> 1, wn = warp & 1;
    const int g = lane >> 2, t = lane & 3;
    const int m0 = blockIdx.y * 128, n0 = blockIdx.x * 128;

    float acc[4][8][4] = {};

    for (int k0 = 0; k0 < 64; k0 += 32) {
        {
            const __nv_bfloat16* srcA = Abase + (size_t)(m0 + tid) * 512 + k0;
            const __nv_bfloat16* srcB = Bbase + (size_t)(n0 + tid) * 512 + k0;
#pragma unroll
            for (int c = 0; c < 4; c++) {
                *(uint4*)&As[tid][c * 8] = *(const uint4*)(srcA + c * 8);
                *(uint4*)&Bs[tid][c * 8] = *(const uint4*)(srcB + c * 8);
            }
        }
        __syncthreads();
#pragma unroll
        for (int kk = 0; kk < 32; kk += 16) {
            uint32_t a[4][4];
#pragma unroll
            for (int mi = 0; mi < 4; mi++)
#pragma unroll
                for (int p = 0; p < 4; p++)
                    a[mi][p] = *(const uint32_t*)&As[wm * 64 + mi * 16 + ((p & 1) << 3) + g]
                                                   [kk + 2 * t + ((p >> 1) << 3)];
#pragma unroll
            for (int ni = 0; ni < 8; ni++) {
                uint32_t b0 = *(const uint32_t*)&Bs[wn * 64 + ni * 8 + g][kk + 2 * t];
                uint32_t b1 = *(const uint32_t*)&Bs[wn * 64 + ni * 8 + g][kk + 2 * t + 8];
#pragma unroll
                for (int mi = 0; mi < 4; mi++) mma16816(acc[mi][ni], a[mi], b0, b1);
            }
        }
        __syncthreads();
    }

    // exp + store p + partial row sums (deterministic: fixed reduce tree)
#pragma unroll
    for (int mi = 0; mi < 4; mi++) {
        size_t r0 = m0 + wm * 64 + mi * 16 + g;
        float rs0 = 0.f, rs1 = 0.f;
#pragma unroll
        for (int ni = 0; ni < 8; ni++) {
            float e0 = __expf(acc[mi][ni][0]);
            float e1 = __expf(acc[mi][ni][1]);
            float e2 = __expf(acc[mi][ni][2]);
            float e3 = __expf(acc[mi][ni][3]);
            rs0 += e0 + e1;  rs1 += e2 + e3;
            int col = n0 + wn * 64 + ni * 8 + 2 * t;
            *(uint32_t*)(C + r0 * 1024 + col) = pack_bf16x2(e0, e1);
            *(uint32_t*)(C + (r0 + 8) * 1024 + col) = pack_bf16x2(e2, e3);
        }
        // reduce over the 4 lanes of the quad (t = 0..3)
#pragma unroll
        for (int o = 1; o < 4; o <<= 1) {
            rs0 += __shfl_xor_sync(0xffffffffu, rs0, o);
            rs1 += __shfl_xor_sync(0xffffffffu, rs1, o);
        }
        if (t == 0) {
            zs[wm * 64 + mi * 16 + g][wn]     = rs0;
            zs[wm * 64 + mi * 16 + g + 8][wn] = rs1;
        }
    }
    __syncthreads();
    if (tid < 128) {
        float zsum = zs[tid][0] + zs[tid][1];
        g_zpart[((size_t)z * 8 + blockIdx.x) * 1024 + m0 + tid] = zsum;
    }
}

// ---------------- 3) fused normalize + competitive combine + AV ----------------
// grid (8, 32): x = 128-row tile, y = bh. Each block produces H1 AND H2 tiles
// (128 rows x 64 head-dims), reading each P element exactly once.
__global__ __launch_bounds__(256, 2) void k_av_fused()
{
    __shared__ __nv_bfloat16 A12s[128][40];
    __shared__ __nv_bfloat16 A21s[128][40];
    __shared__ __nv_bfloat16 V1s[64][40];   // [dim][tok]
    __shared__ __nv_bfloat16 V2s[64][40];
    __shared__ float i1s[128], i2s[128];

    const int bh = blockIdx.y, b = bh >> 3, h = bh & 7;
    const int m0 = blockIdx.x * 128;
    const __nv_bfloat16* P12 = g_S + ((size_t)bh << 20);
    const __nv_bfloat16* P21 = g_S + 33554432ull + ((size_t)bh << 20);
    const __nv_bfloat16* V1 = g_Vh + ((size_t)(b * 2 + 0) * 1024) * 512 + h * 64;
    const __nv_bfloat16* V2 = g_Vh + ((size_t)(b * 2 + 1) * 1024) * 512 + h * 64;
    __nv_bfloat16* C1 = g_attnh + ((size_t)(b * 2 + 0) * 1024) * 512 + h * 64;
    __nv_bfloat16* C2 = g_attnh + ((size_t)(b * 2 + 1) * 1024) * 512 + h * 64;

    const int tid = threadIdx.x, lane = tid & 31, warp = tid >> 5;
    const int wq = warp >> 1, wn = warp & 1;   // 4 m-quarters x 2 col-halves
    const int g = lane >> 2, t = lane & 3;

    if (tid < 128) {
        float z1 = 0.f, z2 = 0.f;
#pragma unroll
        for (int nb = 0; nb < 8; nb++) {
            z1 += g_zpart[(size_t)(bh * 8 + nb) * 1024 + m0 + tid];
            z2 += g_zpart[262144ull + (size_t)(bh * 8 + nb) * 1024 + m0 + tid];
        }
        i1s[tid] = __fdividef(1.f, z1);
        i2s[tid] = __fdividef(1.f, z2);
    }
    __syncthreads();

    const int cr = tid >> 1, cc = (tid & 1) * 16;
    const float i1 = i1s[cr], i2 = i2s[cr];

    float acc1[2][4][4] = {}, acc2[2][4][4] = {};

    for (int k0 = 0; k0 < 1024; k0 += 32) {
        {   // load + normalize + combine: 16 elems of each matrix per thread
            const __nv_bfloat16* p1p = P12 + (size_t)(m0 + cr) * 1024 + k0 + cc;
            const __nv_bfloat16* p2p = P21 + (size_t)(m0 + cr) * 1024 + k0 + cc;
            __nv_bfloat16 p1[16], p2[16], o1[16], o2[16];
            *(uint4*)p1       = *(const uint4*)p1p;
            *(uint4*)(p1 + 8) = *(const uint4*)(p1p + 8);
            *(uint4*)p2       = *(const uint4*)p2p;
            *(uint4*)(p2 + 8) = *(const uint4*)(p2p + 8);
#pragma unroll
            for (int j = 0; j < 16; j++) {
                float s1 = __bfloat162float(p1[j]) * i1;
                float s2 = __bfloat162float(p2[j]) * i2;
                float inv = __fdividef(1.f, s1 + s2 + 1e-6f);
                o1[j] = __float2bfloat16(s1 * inv);
                o2[j] = __float2bfloat16(s2 * inv);
            }
            *(uint4*)&A12s[cr][cc]     = *(uint4*)o1;
            *(uint4*)&A12s[cr][cc + 8] = *(uint4*)(o1 + 8);
            *(uint4*)&A21s[cr][cc]     = *(uint4*)o2;
            *(uint4*)&A21s[cr][cc + 8] = *(uint4*)(o2 + 8);
        }
        {   // V tiles [32 tok][64 dim] -> [dim][tok]
            int kr = tid >> 3, dseg = (tid & 7) * 8;
            const __nv_bfloat16* s1 = V1 + (size_t)(k0 + kr) * 512 + dseg;
            const __nv_bfloat16* s2 = V2 + (size_t)(k0 + kr) * 512 + dseg;
            __nv_bfloat16 t1[8], t2[8];
            *(uint4*)t1 = *(const uint4*)s1;
            *(uint4*)t2 = *(const uint4*)s2;
#pragma unroll
            for (int j = 0; j < 8; j++) { V1s[dseg + j][kr] = t1[j]; V2s[dseg + j][kr] = t2[j]; }
        }
        __syncthreads();
#pragma unroll
        for (int kk = 0; kk < 32; kk += 16) {
            uint32_t a1[2][4], a2[2][4];
#pragma unroll
            for (int mi = 0; mi < 2; mi++)
#pragma unroll
                for (int p = 0; p < 4; p++) {
                    int rr = wq * 32 + mi * 16 + ((p & 1) << 3) + g;
                    int kcol = kk + 2 * t + ((p >> 1) << 3);
                    a1[mi][p] = *(const uint32_t*)&A12s[rr][kcol];
                    a2[mi][p] = *(const uint32_t*)&A21s[rr][kcol];
                }
#pragma unroll
            for (int ni = 0; ni < 4; ni++) {
                int cb = wn * 32 + ni * 8 + g;
                uint32_t b10 = *(const uint32_t*)&V2s[cb][kk + 2 * t];
                uint32_t b11 = *(const uint32_t*)&V2s[cb][kk + 2 * t + 8];
                uint32_t b20 = *(const uint32_t*)&V1s[cb][kk + 2 * t];
                uint32_t b21 = *(const uint32_t*)&V1s[cb][kk + 2 * t + 8];
#pragma unroll
                for (int mi = 0; mi < 2; mi++) {
                    mma16816(acc1[mi][ni], a1[mi], b10, b11);
                    mma16816(acc2[mi][ni], a2[mi], b20, b21);
                }
            }
        }
        __syncthreads();
    }

#pragma unroll
    for (int mi = 0; mi < 2; mi++) {
        int r0 = m0 + wq * 32 + mi * 16 + g;
#pragma unroll
        for (int ni = 0; ni < 4; ni++) {
            int col = wn * 32 + ni * 8 + 2 * t;
            *(uint32_t*)(C1 + (size_t)r0 * 512 + col)       = pack_bf16x2(acc1[mi][ni][0], acc1[mi][ni][1]);
            *(uint32_t*)(C1 + (size_t)(r0 + 8) * 512 + col) = pack_bf16x2(acc1[mi][ni][2], acc1[mi][ni][3]);
            *(uint32_t*)(C2 + (size_t)r0 * 512 + col)       = pack_bf16x2(acc2[mi][ni][0], acc2[mi][ni][1]);
            *(uint32_t*)(C2 + (size_t)(r0 + 8) * 512 + col) = pack_bf16x2(acc2[mi][ni][2], acc2[mi][ni][3]);
        }
    }
}

// ---------------- 4) output projection: g_proj = attn @ Wo^T + bo ----------------
__global__ __launch_bounds__(128) void k_out_mma(const float* __restrict__ bo)
{
    __shared__ __nv_bfloat16 As[128][40];
    __shared__ __nv_bfloat16 Bs[128][40];
    const int tid = threadIdx.x, lane = tid & 31, warp = tid >> 5;
    const int wm = warp >> 1, wn = warp & 1;
    const int g = lane >> 2, t = lane & 3;
    const int m0 = blockIdx.y * 128, n0 = blockIdx.x * 128;
    const __nv_bfloat16* Wo = g_Wh + 3ull * 512 * 512;

    float acc[4][8][4] = {};

    for (int k0 = 0; k0 < 512; k0 += 32) {
        {
            const __nv_bfloat16* srcA = g_attnh + (size_t)(m0 + tid) * 512 + k0;
            const __nv_bfloat16* srcB = Wo + (size_t)(n0 + tid) * 512 + k0;
#pragma unroll
            for (int c = 0; c < 4; c++) {
                *(uint4*)&As[tid][c * 8] = *(const uint4*)(srcA + c * 8);
                *(uint4*)&Bs[tid][c * 8] = *(const uint4*)(srcB + c * 8);
            }
        }
        __syncthreads();
#pragma unroll
        for (int kk = 0; kk < 32; kk += 16) {
            uint32_t a[4][4];
#pragma unroll
            for (int mi = 0; mi < 4; mi++)
#pragma unroll
                for (int p = 0; p < 4; p++)
                    a[mi][p] = *(const uint32_t*)&As[wm * 64 + mi * 16 + ((p & 1) << 3) + g]
                                                   [kk + 2 * t + ((p >> 1) << 3)];
#pragma unroll
            for (int ni = 0; ni < 8; ni++) {
                uint32_t b0 = *(const uint32_t*)&Bs[wn * 64 + ni * 8 + g][kk + 2 * t];
                uint32_t b1 = *(const uint32_t*)&Bs[wn * 64 + ni * 8 + g][kk + 2 * t + 8];
#pragma unroll
                for (int mi = 0; mi < 4; mi++) mma16816(acc[mi][ni], a[mi], b0, b1);
            }
        }
        __syncthreads();
    }

#pragma unroll
    for (int mi = 0; mi < 4; mi++) {
        int r0 = m0 + wm * 64 + mi * 16 + g;
#pragma unroll
        for (int ni = 0; ni < 8; ni++) {
            int col = n0 + wn * 64 + ni * 8 + 2 * t;
            float b0f = bo[col], b1f = bo[col + 1];
            *(float2*)(g_proj + (size_t)r0 * 512 + col) =
                make_float2(acc[mi][ni][0] + b0f, acc[mi][ni][1] + b1f);
            *(float2*)(g_proj + (size_t)(r0 + 8) * 512 + col) =
                make_float2(acc[mi][ni][2] + b0f, acc[mi][ni][3] + b1f);
        }
    }
}

// ---------------- 5) LayerNorm + gate + residual ----------------
__global__ __launch_bounds__(256) void k_ln(
    const float* __restrict__ hidden,
    const float* __restrict__ ln_g, const float* __restrict__ ln_b,
    const float* __restrict__ alpha, float* __restrict__ out)
{
    const int m = blockIdx.x;
    const int s = (m >> 10) & 1;
    const float* p = g_proj + (size_t)m * 512;
    const int tid = threadIdx.x;
    __shared__ float sm[8];

    float x0 = p[tid], x1 = p[tid + 256];
    float sum = blk_red_sum(x0 + x1, sm);
    float sq  = blk_red_sum(x0 * x0 + x1 * x1, sm);
    float mu  = sum * (1.f / 512.f);
    float var = sq * (1.f / 512.f) - mu * mu;
    float rstd = rsqrtf(var + 1e-5f);
    float al = alpha[s];
    size_t base = (size_t)m * 512;

    {
        int e = tid;
        float y = (x0 - mu) * rstd * ln_g[s * 512 + e] + ln_b[s * 512 + e];
        out[base + e] = hidden[base + e] + y * al;
    }
    {
        int e = tid + 256;
        float y = (x1 - mu) * rstd * ln_g[s * 512 + e] + ln_b[s * 512 + e];
        out[base + e] = hidden[base + e] + y * al;
    }
}

// ---------------- launch ----------------
extern "C" void kernel_launch(void* const* d_in, const int* in_sizes, int n_in,
                              void* d_out, int out_size)
{
    const float* hidden = (const float*)d_in[0];
    const float* Wq = (const float*)d_in[1];  const float* bq = (const float*)d_in[2];
    const float* Wk = (const float*)d_in[3];  const float* bk = (const float*)d_in[4];
    const float* Wv = (const float*)d_in[5];  const float* bv = (const float*)d_in[6];
    const float* Wo = (const float*)d_in[7];  const float* bo = (const float*)d_in[8];
    const float* lng = (const float*)d_in[9]; const float* lnb = (const float*)d_in[10];
    const float* alpha = (const float*)d_in[11];
    float* out = (float*)d_out;

    k_prep<<<5120, 256>>>(hidden, Wq, Wk, Wv, Wo);
    k_qkv_mma<<<dim3(12, 64), 128>>>(bq, bk, bv);
    k_scores_mma<<<dim3(8, 8, 64), 128>>>();
    k_av_fused<<<dim3(8, 32), 256>>>();
    k_out_mma<<<dim3(4, 64), 128>>>(bo);
    k_ln<<<8192, 256>>>(hidden, lng, lnb, alpha, out);
}

// round 8
// speedup vs baseline: 1.4210x; 1.4210x over previous
#include <cuda_runtime.h>
#include <cuda_bf16.h>
#include <stdint.h>
#include <math.h>

// Shapes (fixed): B=4, S=2, T=1024, D=512, H=8, HD=64, M = B*S*T = 8192
// bf16 tensor-core GEMMs (mma.sync m16n8k16, fp32 accum).
// scores stores p=exp(logit) (logits O(1), no max needed) + deterministic
// partial row sums; k_zinv folds partials -> 1/z; k_combine2 is pure
// elementwise streaming; k_av_mma consumes normalized probs.

// ---------------- device workspaces ----------------
__device__ __nv_bfloat16 g_Xh[8192ull * 512];
__device__ __nv_bfloat16 g_Wh[4ull * 512 * 512];  // [Wq;Wk;Wv;Wo]
__device__ __nv_bfloat16 g_Qh[8192ull * 512];     // Q*0.125 (scale folded)
__device__ __nv_bfloat16 g_Kh[8192ull * 512];
__device__ __nv_bfloat16 g_Vh[8192ull * 512];
__device__ __nv_bfloat16 g_S[67108864ull];        // [ss][bh][q][k] probs (in place)
__device__ float         g_zpart[524288];         // [ss][bh][nblk(8)][q]
__device__ float         g_zinv[65536];           // [ss][bh][q] 1/rowsum
__device__ __nv_bfloat16 g_attnh[8192ull * 512];
__device__ float         g_proj[8192ull * 512];

// ---------------- helpers ----------------
__device__ __forceinline__ uint32_t pack_bf16x2(float a, float b) {
    __nv_bfloat162 h = __floats2bfloat162_rn(a, b);
    return *reinterpret_cast<uint32_t*>(&h);
}

__device__ __forceinline__ void mma16816(float* c, const uint32_t* a, uint32_t b0, uint32_t b1) {
    asm volatile(
        "mma.sync.aligned.m16n8k16.row.col.f32.bf16.bf16.f32 "
        "{%0,%1,%2,%3}, {%4,%5,%6,%7}, {%8,%9}, {%0,%1,%2,%3};\n"
        : "+f"(c[0]), "+f"(c[1]), "+f"(c[2]), "+f"(c[3])
        : "r"(a[0]), "r"(a[1]), "r"(a[2]), "r"(a[3]), "r"(b0), "r"(b1));
}

__device__ __forceinline__ float blk_red_sum(float v, float* sm) {
    int lane = threadIdx.x & 31, wid = threadIdx.x >> 5;
#pragma unroll
    for (int o = 16; o; o >>= 1) v += __shfl_xor_sync(0xffffffffu, v, o);
    if (lane == 0) sm[wid] = v;
    __syncthreads();
    float r = 0.f;
#pragma unroll
    for (int i = 0; i < 8; i++) r += sm[i];
    __syncthreads();
    return r;
}

// ---------------- 0) convert inputs to bf16 ----------------
__global__ __launch_bounds__(256) void k_prep(
    const float* __restrict__ X,
    const float* __restrict__ Wq, const float* __restrict__ Wk,
    const float* __restrict__ Wv, const float* __restrict__ Wo)
{
    const int idx = blockIdx.x * 256 + threadIdx.x;
    if (idx < 1048576) {
        float4 v = ((const float4*)X)[idx];
        uint2 o; o.x = pack_bf16x2(v.x, v.y); o.y = pack_bf16x2(v.z, v.w);
        ((uint2*)g_Xh)[idx] = o;
    } else {
        int j = idx - 1048576;
        int w = j >> 16;
        const float4* src = (w == 0) ? (const float4*)Wq : (w == 1) ? (const float4*)Wk
                          : (w == 2) ? (const float4*)Wv : (const float4*)Wo;
        float4 v = src[j & 65535];
        uint2 o; o.x = pack_bf16x2(v.x, v.y); o.y = pack_bf16x2(v.z, v.w);
        ((uint2*)g_Wh)[j] = o;
    }
}

// ---------------- 1) QKV projection (bf16 mma) ----------------
__global__ __launch_bounds__(128) void k_qkv_mma(
    const float* __restrict__ bq, const float* __restrict__ bk, const float* __restrict__ bv)
{
    __shared__ __nv_bfloat16 As[128][40];
    __shared__ __nv_bfloat16 Bs[128][40];
    const int tid = threadIdx.x, lane = tid & 31, warp = tid >> 5;
    const int wm = warp >> 1, wn = warp & 1;
    const int g = lane >> 2, t = lane & 3;
    const int m0 = blockIdx.y * 128, n0g = blockIdx.x * 128;

    float acc[4][8][4] = {};

    for (int k0 = 0; k0 < 512; k0 += 32) {
        {
            const __nv_bfloat16* srcA = g_Xh + (size_t)(m0 + tid) * 512 + k0;
            const __nv_bfloat16* srcB = g_Wh + (size_t)(n0g + tid) * 512 + k0;
#pragma unroll
            for (int c = 0; c < 4; c++) {
                *(uint4*)&As[tid][c * 8] = *(const uint4*)(srcA + c * 8);
                *(uint4*)&Bs[tid][c * 8] = *(const uint4*)(srcB + c * 8);
            }
        }
        __syncthreads();
#pragma unroll
        for (int kk = 0; kk < 32; kk += 16) {
            uint32_t a[4][4];
#pragma unroll
            for (int mi = 0; mi < 4; mi++)
#pragma unroll
                for (int p = 0; p < 4; p++)
                    a[mi][p] = *(const uint32_t*)&As[wm * 64 + mi * 16 + ((p & 1) << 3) + g]
                                                   [kk + 2 * t + ((p >> 1) << 3)];
#pragma unroll
            for (int ni = 0; ni < 8; ni++) {
                uint32_t b0 = *(const uint32_t*)&Bs[wn * 64 + ni * 8 + g][kk + 2 * t];
                uint32_t b1 = *(const uint32_t*)&Bs[wn * 64 + ni * 8 + g][kk + 2 * t + 8];
#pragma unroll
                for (int mi = 0; mi < 4; mi++) mma16816(acc[mi][ni], a[mi], b0, b1);
            }
        }
        __syncthreads();
    }

    const int mat = n0g >> 9, nloc = n0g & 511;
    const float* bias = (mat == 0) ? bq : (mat == 1) ? bk : bv;
    __nv_bfloat16* out = (mat == 0) ? g_Qh : (mat == 1) ? g_Kh : g_Vh;
    const float scale = (mat == 0) ? 0.125f : 1.0f;

#pragma unroll
    for (int mi = 0; mi < 4; mi++) {
        int r0 = m0 + wm * 64 + mi * 16 + g;
#pragma unroll
        for (int ni = 0; ni < 8; ni++) {
            int col = nloc + wn * 64 + ni * 8 + 2 * t;
            float b0f = bias[col], b1f = bias[col + 1];
            *(uint32_t*)(out + (size_t)r0 * 512 + col) =
                pack_bf16x2((acc[mi][ni][0] + b0f) * scale, (acc[mi][ni][1] + b1f) * scale);
            *(uint32_t*)(out + (size_t)(r0 + 8) * 512 + col) =
                pack_bf16x2((acc[mi][ni][2] + b0f) * scale, (acc[mi][ni][3] + b1f) * scale);
        }
    }
}

// ---------------- 2) scores: p = exp(Qs_ss @ K_{1-ss}^T) + partial row sums ----
// grid (8, 8, 64): x = nblk, y = mblk, z = ss*32 + bh.
__global__ __launch_bounds__(128) void k_scores_mma()
{
    __shared__ __nv_bfloat16 As[128][40];
    __shared__ __nv_bfloat16 Bs[128][40];
    __shared__ float zs[128][2];
    const int z = blockIdx.z;
    const int ss = z >> 5, bh = z & 31, b = bh >> 3, h = bh & 7;
    const __nv_bfloat16* Abase = g_Qh + ((size_t)(b * 2 + ss) * 1024) * 512 + h * 64;
    const __nv_bfloat16* Bbase = g_Kh + ((size_t)(b * 2 + (1 - ss)) * 1024) * 512 + h * 64;
    __nv_bfloat16* C = g_S + ((size_t)z << 20);

    const int tid = threadIdx.x, lane = tid & 31, warp = tid >> 5;
    const int wm = warp >> 1, wn = warp & 1;
    const int g = lane >> 2, t = lane & 3;
    const int m0 = blockIdx.y * 128, n0 = blockIdx.x * 128;

    float acc[4][8][4] = {};

    for (int k0 = 0; k0 < 64; k0 += 32) {
        {
            const __nv_bfloat16* srcA = Abase + (size_t)(m0 + tid) * 512 + k0;
            const __nv_bfloat16* srcB = Bbase + (size_t)(n0 + tid) * 512 + k0;
#pragma unroll
            for (int c = 0; c < 4; c++) {
                *(uint4*)&As[tid][c * 8] = *(const uint4*)(srcA + c * 8);
                *(uint4*)&Bs[tid][c * 8] = *(const uint4*)(srcB + c * 8);
            }
        }
        __syncthreads();
#pragma unroll
        for (int kk = 0; kk < 32; kk += 16) {
            uint32_t a[4][4];
#pragma unroll
            for (int mi = 0; mi < 4; mi++)
#pragma unroll
                for (int p = 0; p < 4; p++)
                    a[mi][p] = *(const uint32_t*)&As[wm * 64 + mi * 16 + ((p & 1) << 3) + g]
                                                   [kk + 2 * t + ((p >> 1) << 3)];
#pragma unroll
            for (int ni = 0; ni < 8; ni++) {
                uint32_t b0 = *(const uint32_t*)&Bs[wn * 64 + ni * 8 + g][kk + 2 * t];
                uint32_t b1 = *(const uint32_t*)&Bs[wn * 64 + ni * 8 + g][kk + 2 * t + 8];
#pragma unroll
                for (int mi = 0; mi < 4; mi++) mma16816(acc[mi][ni], a[mi], b0, b1);
            }
        }
        __syncthreads();
    }

#pragma unroll
    for (int mi = 0; mi < 4; mi++) {
        size_t r0 = m0 + wm * 64 + mi * 16 + g;
        float rs0 = 0.f, rs1 = 0.f;
#pragma unroll
        for (int ni = 0; ni < 8; ni++) {
            float e0 = __expf(acc[mi][ni][0]);
            float e1 = __expf(acc[mi][ni][1]);
            float e2 = __expf(acc[mi][ni][2]);
            float e3 = __expf(acc[mi][ni][3]);
            rs0 += e0 + e1;  rs1 += e2 + e3;
            int col = n0 + wn * 64 + ni * 8 + 2 * t;
            *(uint32_t*)(C + r0 * 1024 + col) = pack_bf16x2(e0, e1);
            *(uint32_t*)(C + (r0 + 8) * 1024 + col) = pack_bf16x2(e2, e3);
        }
#pragma unroll
        for (int o = 1; o < 4; o <<= 1) {
            rs0 += __shfl_xor_sync(0xffffffffu, rs0, o);
            rs1 += __shfl_xor_sync(0xffffffffu, rs1, o);
        }
        if (t == 0) {
            zs[wm * 64 + mi * 16 + g][wn]     = rs0;
            zs[wm * 64 + mi * 16 + g + 8][wn] = rs1;
        }
    }
    __syncthreads();
    if (tid < 128) {
        float zsum = zs[tid][0] + zs[tid][1];
        g_zpart[((size_t)z * 8 + blockIdx.x) * 1024 + m0 + tid] = zsum;
    }
}

// ---------------- 3a) fold partial sums -> reciprocal ----------------
// grid 128 x 512: i over 65536 rows ([ss][bh][q])
__global__ __launch_bounds__(512) void k_zinv()
{
    const int i = blockIdx.x * 512 + threadIdx.x;   // z*1024 + q, z in [0,64)
    const int z = i >> 10, q = i & 1023;
    float s = 0.f;
#pragma unroll
    for (int nb = 0; nb < 8; nb++) s += g_zpart[((size_t)z * 8 + nb) * 1024 + q];
    g_zinv[i] = __fdividef(1.f, s);
}

// ---------------- 3b) elementwise normalize + competitive combine ----------------
// 4M uint4 slots per matrix; 128 uint4 per row. grid 16384 x 256.
__global__ __launch_bounds__(256) void k_combine2()
{
    const int idx = blockIdx.x * 256 + threadIdx.x;   // [0, 4194304)
    const int r = idx >> 7;                           // row in [0, 32768)
    const float i1 = g_zinv[r];
    const float i2 = g_zinv[32768 + r];

    uint4 u1 = ((const uint4*)g_S)[idx];
    uint4 u2 = ((const uint4*)g_S)[4194304 + idx];
    __nv_bfloat16* p1 = (__nv_bfloat16*)&u1;
    __nv_bfloat16* p2 = (__nv_bfloat16*)&u2;
    __nv_bfloat16 o1[8], o2[8];
#pragma unroll
    for (int j = 0; j < 8; j++) {
        float s1 = __bfloat162float(p1[j]) * i1;
        float s2 = __bfloat162float(p2[j]) * i2;
        float inv = __fdividef(1.f, s1 + s2 + 1e-6f);
        o1[j] = __float2bfloat16(s1 * inv);
        o2[j] = __float2bfloat16(s2 * inv);
    }
    ((uint4*)g_S)[idx] = *(uint4*)o1;
    ((uint4*)g_S)[4194304 + idx] = *(uint4*)o2;
}

// ---------------- 4) AV: H_ss = A_ss(1024x1024) @ V_{1-ss}(1024x64) ----------------
// grid (8, 64). BM=128, BN=64, BK=32, warp tile 64x32 (2x2 warps).
__global__ __launch_bounds__(128) void k_av_mma()
{
    __shared__ __nv_bfloat16 As[128][40];
    __shared__ __nv_bfloat16 Vs[64][40];           // [dim][token]
    const int z = blockIdx.y;
    const int ss = z >> 5, bh = z & 31, b = bh >> 3, h = bh & 7;
    const __nv_bfloat16* Abase = g_S + ((size_t)(ss * 32 + bh) << 20);
    const __nv_bfloat16* Vbase = g_Vh + ((size_t)(b * 2 + (1 - ss)) * 1024) * 512 + h * 64;
    __nv_bfloat16* Cbase = g_attnh + ((size_t)(b * 2 + ss) * 1024) * 512 + h * 64;

    const int tid = threadIdx.x, lane = tid & 31, warp = tid >> 5;
    const int wm = warp >> 1, wn = warp & 1;
    const int g = lane >> 2, t = lane & 3;
    const int m0 = blockIdx.x * 128;

    float acc[4][4][4] = {};

    for (int k0 = 0; k0 < 1024; k0 += 32) {
        {
            const __nv_bfloat16* srcA = Abase + (size_t)(m0 + tid) * 1024 + k0;
#pragma unroll
            for (int c = 0; c < 4; c++) *(uint4*)&As[tid][c * 8] = *(const uint4*)(srcA + c * 8);
        }
        {
            int kr = tid >> 2, dseg = (tid & 3) * 16;
            const __nv_bfloat16* src = Vbase + (size_t)(k0 + kr) * 512 + dseg;
            __nv_bfloat16 tmp[16];
            *(uint4*)tmp = *(const uint4*)src;
            *(uint4*)(tmp + 8) = *(const uint4*)(src + 8);
#pragma unroll
            for (int j = 0; j < 16; j++) Vs[dseg + j][kr] = tmp[j];
        }
        __syncthreads();
#pragma unroll
        for (int kk = 0; kk < 32; kk += 16) {
            uint32_t a[4][4];
#pragma unroll
            for (int mi = 0; mi < 4; mi++)
#pragma unroll
                for (int p = 0; p < 4; p++)
                    a[mi][p] = *(const uint32_t*)&As[wm * 64 + mi * 16 + ((p & 1) << 3) + g]
                                                   [kk + 2 * t + ((p >> 1) << 3)];
#pragma unroll
            for (int ni = 0; ni < 4; ni++) {
                uint32_t b0 = *(const uint32_t*)&Vs[wn * 32 + ni * 8 + g][kk + 2 * t];
                uint32_t b1 = *(const uint32_t*)&Vs[wn * 32 + ni * 8 + g][kk + 2 * t + 8];
#pragma unroll
                for (int mi = 0; mi < 4; mi++) mma16816(acc[mi][ni], a[mi], b0, b1);
            }
        }
        __syncthreads();
    }

#pragma unroll
    for (int mi = 0; mi < 4; mi++) {
        int r0 = m0 + wm * 64 + mi * 16 + g;
#pragma unroll
        for (int ni = 0; ni < 4; ni++) {
            int col = wn * 32 + ni * 8 + 2 * t;
            *(uint32_t*)(Cbase + (size_t)r0 * 512 + col)       = pack_bf16x2(acc[mi][ni][0], acc[mi][ni][1]);
            *(uint32_t*)(Cbase + (size_t)(r0 + 8) * 512 + col) = pack_bf16x2(acc[mi][ni][2], acc[mi][ni][3]);
        }
    }
}

// ---------------- 5) output projection: g_proj = attn @ Wo^T + bo ----------------
__global__ __launch_bounds__(128) void k_out_mma(const float* __restrict__ bo)
{
    __shared__ __nv_bfloat16 As[128][40];
    __shared__ __nv_bfloat16 Bs[128][40];
    const int tid = threadIdx.x, lane = tid & 31, warp = tid >> 5;
    const int wm = warp >> 1, wn = warp & 1;
    const int g = lane >> 2, t = lane & 3;
    const int m0 = blockIdx.y * 128, n0 = blockIdx.x * 128;
    const __nv_bfloat16* Wo = g_Wh + 3ull * 512 * 512;

    float acc[4][8][4] = {};

    for (int k0 = 0; k0 < 512; k0 += 32) {
        {
            const __nv_bfloat16* srcA = g_attnh + (size_t)(m0 + tid) * 512 + k0;
            const __nv_bfloat16* srcB = Wo + (size_t)(n0 + tid) * 512 + k0;
#pragma unroll
            for (int c = 0; c < 4; c++) {
                *(uint4*)&As[tid][c * 8] = *(const uint4*)(srcA + c * 8);
                *(uint4*)&Bs[tid][c * 8] = *(const uint4*)(srcB + c * 8);
            }
        }
        __syncthreads();
#pragma unroll
        for (int kk = 0; kk < 32; kk += 16) {
            uint32_t a[4][4];
#pragma unroll
            for (int mi = 0; mi < 4; mi++)
#pragma unroll
                for (int p = 0; p < 4; p++)
                    a[mi][p] = *(const uint32_t*)&As[wm * 64 + mi * 16 + ((p & 1) << 3) + g]
                                                   [kk + 2 * t + ((p >> 1) << 3)];
#pragma unroll
            for (int ni = 0; ni < 8; ni++) {
                uint32_t b0 = *(const uint32_t*)&Bs[wn * 64 + ni * 8 + g][kk + 2 * t];
                uint32_t b1 = *(const uint32_t*)&Bs[wn * 64 + ni * 8 + g][kk + 2 * t + 8];
#pragma unroll
                for (int mi = 0; mi < 4; mi++) mma16816(acc[mi][ni], a[mi], b0, b1);
            }
        }
        __syncthreads();
    }

#pragma unroll
    for (int mi = 0; mi < 4; mi++) {
        int r0 = m0 + wm * 64 + mi * 16 + g;
#pragma unroll
        for (int ni = 0; ni < 8; ni++) {
            int col = n0 + wn * 64 + ni * 8 + 2 * t;
            float b0f = bo[col], b1f = bo[col + 1];
            *(float2*)(g_proj + (size_t)r0 * 512 + col) =
                make_float2(acc[mi][ni][0] + b0f, acc[mi][ni][1] + b1f);
            *(float2*)(g_proj + (size_t)(r0 + 8) * 512 + col) =
                make_float2(acc[mi][ni][2] + b0f, acc[mi][ni][3] + b1f);
        }
    }
}

// ---------------- 6) LayerNorm + gate + residual ----------------
__global__ __launch_bounds__(256) void k_ln(
    const float* __restrict__ hidden,
    const float* __restrict__ ln_g, const float* __restrict__ ln_b,
    const float* __restrict__ alpha, float* __restrict__ out)
{
    const int m = blockIdx.x;
    const int s = (m >> 10) & 1;
    const float* p = g_proj + (size_t)m * 512;
    const int tid = threadIdx.x;
    __shared__ float sm[8];

    float x0 = p[tid], x1 = p[tid + 256];
    float sum = blk_red_sum(x0 + x1, sm);
    float sq  = blk_red_sum(x0 * x0 + x1 * x1, sm);
    float mu  = sum * (1.f / 512.f);
    float var = sq * (1.f / 512.f) - mu * mu;
    float rstd = rsqrtf(var + 1e-5f);
    float al = alpha[s];
    size_t base = (size_t)m * 512;

    {
        int e = tid;
        float y = (x0 - mu) * rstd * ln_g[s * 512 + e] + ln_b[s * 512 + e];
        out[base + e] = hidden[base + e] + y * al;
    }
    {
        int e = tid + 256;
        float y = (x1 - mu) * rstd * ln_g[s * 512 + e] + ln_b[s * 512 + e];
        out[base + e] = hidden[base + e] + y * al;
    }
}

// ---------------- launch ----------------
extern "C" void kernel_launch(void* const* d_in, const int* in_sizes, int n_in,
                              void* d_out, int out_size)
{
    const float* hidden = (const float*)d_in[0];
    const float* Wq = (const float*)d_in[1];  const float* bq = (const float*)d_in[2];
    const float* Wk = (const float*)d_in[3];  const float* bk = (const float*)d_in[4];
    const float* Wv = (const float*)d_in[5];  const float* bv = (const float*)d_in[6];
    const float* Wo = (const float*)d_in[7];  const float* bo = (const float*)d_in[8];
    const float* lng = (const float*)d_in[9]; const float* lnb = (const float*)d_in[10];
    const float* alpha = (const float*)d_in[11];
    float* out = (float*)d_out;

    k_prep<<<5120, 256>>>(hidden, Wq, Wk, Wv, Wo);
    k_qkv_mma<<<dim3(12, 64), 128>>>(bq, bk, bv);
    k_scores_mma<<<dim3(8, 8, 64), 128>>>();
    k_zinv<<<128, 512>>>();
    k_combine2<<<16384, 256>>>();
    k_av_mma<<<dim3(8, 64), 128>>>();
    k_out_mma<<<dim3(4, 64), 128>>>(bo);
    k_ln<<<8192, 256>>>(hidden, lng, lnb, alpha, out);
}

// round 9
// speedup vs baseline: 1.6401x; 1.1541x over previous
#include <cuda_runtime.h>
#include <cuda_bf16.h>
#include <stdint.h>
#include <math.h>

// Shapes (fixed): B=4, S=2, T=1024, D=512, H=8, HD=64, M = B*S*T = 8192
// bf16 tensor-core GEMMs (mma.sync m16n8k16, fp32 accum), 2-stage cp.async
// double-buffered pipelines. scores stores p=exp(logit) + partial row sums;
// k_zinv folds partials -> 1/z; k_combine2 is elementwise streaming.

// ---------------- device workspaces ----------------
__device__ __nv_bfloat16 g_Xh[8192ull * 512];
__device__ __nv_bfloat16 g_Wh[4ull * 512 * 512];  // [Wq;Wk;Wv;Wo]
__device__ __nv_bfloat16 g_Qh[8192ull * 512];     // Q*0.125 (scale folded)
__device__ __nv_bfloat16 g_Kh[8192ull * 512];
__device__ __nv_bfloat16 g_Vh[8192ull * 512];
__device__ __nv_bfloat16 g_S[67108864ull];        // [ss][bh][q][k] probs (in place)
__device__ float         g_zpart[524288];         // [ss][bh][nblk(8)][q]
__device__ float         g_zinv[65536];           // [ss][bh][q] 1/rowsum
__device__ __nv_bfloat16 g_attnh[8192ull * 512];
__device__ float         g_proj[8192ull * 512];

// ---------------- helpers ----------------
__device__ __forceinline__ uint32_t pack_bf16x2(float a, float b) {
    __nv_bfloat162 h = __floats2bfloat162_rn(a, b);
    return *reinterpret_cast<uint32_t*>(&h);
}

__device__ __forceinline__ void mma16816(float* c, const uint32_t* a, uint32_t b0, uint32_t b1) {
    asm volatile(
        "mma.sync.aligned.m16n8k16.row.col.f32.bf16.bf16.f32 "
        "{%0,%1,%2,%3}, {%4,%5,%6,%7}, {%8,%9}, {%0,%1,%2,%3};\n"
        : "+f"(c[0]), "+f"(c[1]), "+f"(c[2]), "+f"(c[3])
        : "r"(a[0]), "r"(a[1]), "r"(a[2]), "r"(a[3]), "r"(b0), "r"(b1));
}

__device__ __forceinline__ void cpa16(void* smem, const void* g) {
    uint32_t s = (uint32_t)__cvta_generic_to_shared(smem);
    asm volatile("cp.async.cg.shared.global [%0], [%1], 16;" :: "r"(s), "l"(g));
}
#define CPA_COMMIT asm volatile("cp.async.commit_group;")
#define CPA_WAIT0  asm volatile("cp.async.wait_group 0;")

__device__ __forceinline__ float blk_red_sum(float v, float* sm) {
    int lane = threadIdx.x & 31, wid = threadIdx.x >> 5;
#pragma unroll
    for (int o = 16; o; o >>= 1) v += __shfl_xor_sync(0xffffffffu, v, o);
    if (lane == 0) sm[wid] = v;
    __syncthreads();
    float r = 0.f;
#pragma unroll
    for (int i = 0; i < 8; i++) r += sm[i];
    __syncthreads();
    return r;
}

// ---------------- 0) convert inputs to bf16 ----------------
__global__ __launch_bounds__(256) void k_prep(
    const float* __restrict__ X,
    const float* __restrict__ Wq, const float* __restrict__ Wk,
    const float* __restrict__ Wv, const float* __restrict__ Wo)
{
    const int idx = blockIdx.x * 256 + threadIdx.x;
    if (idx < 1048576) {
        float4 v = ((const float4*)X)[idx];
        uint2 o; o.x = pack_bf16x2(v.x, v.y); o.y = pack_bf16x2(v.z, v.w);
        ((uint2*)g_Xh)[idx] = o;
    } else {
        int j = idx - 1048576;
        int w = j >> 16;
        const float4* src = (w == 0) ? (const float4*)Wq : (w == 1) ? (const float4*)Wk
                          : (w == 2) ? (const float4*)Wv : (const float4*)Wo;
        float4 v = src[j & 65535];
        uint2 o; o.x = pack_bf16x2(v.x, v.y); o.y = pack_bf16x2(v.z, v.w);
        ((uint2*)g_Wh)[j] = o;
    }
}

// ---------------- 1) QKV projection (bf16 mma, cp.async 2-stage) ----------------
// grid (12, 64), 128 threads. BM=BN=128, BK=32, warp tile 64x64.
__global__ __launch_bounds__(128) void k_qkv_mma(
    const float* __restrict__ bq, const float* __restrict__ bk, const float* __restrict__ bv)
{
    __shared__ __nv_bfloat16 As[2][128][40];
    __shared__ __nv_bfloat16 Bs[2][128][40];
    const int tid = threadIdx.x, lane = tid & 31, warp = tid >> 5;
    const int wm = warp >> 1, wn = warp & 1;
    const int g = lane >> 2, t = lane & 3;
    const int m0 = blockIdx.y * 128, n0g = blockIdx.x * 128;

    const __nv_bfloat16* srcA0 = g_Xh + (size_t)(m0 + tid) * 512;
    const __nv_bfloat16* srcB0 = g_Wh + (size_t)(n0g + tid) * 512;

    float acc[4][8][4] = {};

#define QKV_ISSUE(K0, BUF)                                            \
    {                                                                 \
        _Pragma("unroll")                                             \
        for (int c = 0; c < 4; c++) {                                 \
            cpa16(&As[BUF][tid][c * 8], srcA0 + (K0) + c * 8);        \
            cpa16(&Bs[BUF][tid][c * 8], srcB0 + (K0) + c * 8);        \
        }                                                             \
    }

    QKV_ISSUE(0, 0); CPA_COMMIT;

    for (int it = 0; it < 16; it++) {
        CPA_WAIT0;
        __syncthreads();
        if (it + 1 < 16) { QKV_ISSUE((it + 1) * 32, (it + 1) & 1); CPA_COMMIT; }
        const int cb = it & 1;
#pragma unroll
        for (int kk = 0; kk < 32; kk += 16) {
            uint32_t a[4][4];
#pragma unroll
            for (int mi = 0; mi < 4; mi++)
#pragma unroll
                for (int p = 0; p < 4; p++)
                    a[mi][p] = *(const uint32_t*)&As[cb][wm * 64 + mi * 16 + ((p & 1) << 3) + g]
                                                   [kk + 2 * t + ((p >> 1) << 3)];
#pragma unroll
            for (int ni = 0; ni < 8; ni++) {
                uint32_t b0 = *(const uint32_t*)&Bs[cb][wn * 64 + ni * 8 + g][kk + 2 * t];
                uint32_t b1 = *(const uint32_t*)&Bs[cb][wn * 64 + ni * 8 + g][kk + 2 * t + 8];
#pragma unroll
                for (int mi = 0; mi < 4; mi++) mma16816(acc[mi][ni], a[mi], b0, b1);
            }
        }
        __syncthreads();
    }
#undef QKV_ISSUE

    const int mat = n0g >> 9, nloc = n0g & 511;
    const float* bias = (mat == 0) ? bq : (mat == 1) ? bk : bv;
    __nv_bfloat16* out = (mat == 0) ? g_Qh : (mat == 1) ? g_Kh : g_Vh;
    const float scale = (mat == 0) ? 0.125f : 1.0f;

#pragma unroll
    for (int mi = 0; mi < 4; mi++) {
        int r0 = m0 + wm * 64 + mi * 16 + g;
#pragma unroll
        for (int ni = 0; ni < 8; ni++) {
            int col = nloc + wn * 64 + ni * 8 + 2 * t;
            float b0f = bias[col], b1f = bias[col + 1];
            *(uint32_t*)(out + (size_t)r0 * 512 + col) =
                pack_bf16x2((acc[mi][ni][0] + b0f) * scale, (acc[mi][ni][1] + b1f) * scale);
            *(uint32_t*)(out + (size_t)(r0 + 8) * 512 + col) =
                pack_bf16x2((acc[mi][ni][2] + b0f) * scale, (acc[mi][ni][3] + b1f) * scale);
        }
    }
}

// ---------------- 2) scores: p = exp(Qs_ss @ K_{1-ss}^T) + partial row sums ----
// grid (8, 8, 64): x = nblk, y = mblk, z = ss*32 + bh.
__global__ __launch_bounds__(128) void k_scores_mma()
{
    __shared__ __nv_bfloat16 As[2][128][40];
    __shared__ __nv_bfloat16 Bs[2][128][40];
    __shared__ float zs[128][2];
    const int z = blockIdx.z;
    const int ss = z >> 5, bh = z & 31, b = bh >> 3, h = bh & 7;
    const __nv_bfloat16* Abase = g_Qh + ((size_t)(b * 2 + ss) * 1024) * 512 + h * 64;
    const __nv_bfloat16* Bbase = g_Kh + ((size_t)(b * 2 + (1 - ss)) * 1024) * 512 + h * 64;
    __nv_bfloat16* C = g_S + ((size_t)z << 20);

    const int tid = threadIdx.x, lane = tid & 31, warp = tid >> 5;
    const int wm = warp >> 1, wn = warp & 1;
    const int g = lane >> 2, t = lane & 3;
    const int m0 = blockIdx.y * 128, n0 = blockIdx.x * 128;

    const __nv_bfloat16* srcA0 = Abase + (size_t)(m0 + tid) * 512;
    const __nv_bfloat16* srcB0 = Bbase + (size_t)(n0 + tid) * 512;

    float acc[4][8][4] = {};

#define SC_ISSUE(K0, BUF)                                             \
    {                                                                 \
        _Pragma("unroll")                                             \
        for (int c = 0; c < 4; c++) {                                 \
            cpa16(&As[BUF][tid][c * 8], srcA0 + (K0) + c * 8);        \
            cpa16(&Bs[BUF][tid][c * 8], srcB0 + (K0) + c * 8);        \
        }                                                             \
    }

    SC_ISSUE(0, 0); CPA_COMMIT;

    for (int it = 0; it < 2; it++) {
        CPA_WAIT0;
        __syncthreads();
        if (it + 1 < 2) { SC_ISSUE(32, 1); CPA_COMMIT; }
        const int cb = it & 1;
#pragma unroll
        for (int kk = 0; kk < 32; kk += 16) {
            uint32_t a[4][4];
#pragma unroll
            for (int mi = 0; mi < 4; mi++)
#pragma unroll
                for (int p = 0; p < 4; p++)
                    a[mi][p] = *(const uint32_t*)&As[cb][wm * 64 + mi * 16 + ((p & 1) << 3) + g]
                                                   [kk + 2 * t + ((p >> 1) << 3)];
#pragma unroll
            for (int ni = 0; ni < 8; ni++) {
                uint32_t b0 = *(const uint32_t*)&Bs[cb][wn * 64 + ni * 8 + g][kk + 2 * t];
                uint32_t b1 = *(const uint32_t*)&Bs[cb][wn * 64 + ni * 8 + g][kk + 2 * t + 8];
#pragma unroll
                for (int mi = 0; mi < 4; mi++) mma16816(acc[mi][ni], a[mi], b0, b1);
            }
        }
        __syncthreads();
    }
#undef SC_ISSUE

#pragma unroll
    for (int mi = 0; mi < 4; mi++) {
        size_t r0 = m0 + wm * 64 + mi * 16 + g;
        float rs0 = 0.f, rs1 = 0.f;
#pragma unroll
        for (int ni = 0; ni < 8; ni++) {
            float e0 = __expf(acc[mi][ni][0]);
            float e1 = __expf(acc[mi][ni][1]);
            float e2 = __expf(acc[mi][ni][2]);
            float e3 = __expf(acc[mi][ni][3]);
            rs0 += e0 + e1;  rs1 += e2 + e3;
            int col = n0 + wn * 64 + ni * 8 + 2 * t;
            *(uint32_t*)(C + r0 * 1024 + col) = pack_bf16x2(e0, e1);
            *(uint32_t*)(C + (r0 + 8) * 1024 + col) = pack_bf16x2(e2, e3);
        }
#pragma unroll
        for (int o = 1; o < 4; o <<= 1) {
            rs0 += __shfl_xor_sync(0xffffffffu, rs0, o);
            rs1 += __shfl_xor_sync(0xffffffffu, rs1, o);
        }
        if (t == 0) {
            zs[wm * 64 + mi * 16 + g][wn]     = rs0;
            zs[wm * 64 + mi * 16 + g + 8][wn] = rs1;
        }
    }
    __syncthreads();
    if (tid < 128) {
        float zsum = zs[tid][0] + zs[tid][1];
        g_zpart[((size_t)z * 8 + blockIdx.x) * 1024 + m0 + tid] = zsum;
    }
}

// ---------------- 3a) fold partial sums -> reciprocal ----------------
__global__ __launch_bounds__(512) void k_zinv()
{
    const int i = blockIdx.x * 512 + threadIdx.x;
    const int z = i >> 10, q = i & 1023;
    float s = 0.f;
#pragma unroll
    for (int nb = 0; nb < 8; nb++) s += g_zpart[((size_t)z * 8 + nb) * 1024 + q];
    g_zinv[i] = __fdividef(1.f, s);
}

// ---------------- 3b) elementwise normalize + competitive combine ----------------
__global__ __launch_bounds__(256) void k_combine2()
{
    const int idx = blockIdx.x * 256 + threadIdx.x;   // [0, 4194304)
    const int r = idx >> 7;                           // row in [0, 32768)
    const float i1 = g_zinv[r];
    const float i2 = g_zinv[32768 + r];

    uint4 u1 = ((const uint4*)g_S)[idx];
    uint4 u2 = ((const uint4*)g_S)[4194304 + idx];
    __nv_bfloat16* p1 = (__nv_bfloat16*)&u1;
    __nv_bfloat16* p2 = (__nv_bfloat16*)&u2;
    __nv_bfloat16 o1[8], o2[8];
#pragma unroll
    for (int j = 0; j < 8; j++) {
        float s1 = __bfloat162float(p1[j]) * i1;
        float s2 = __bfloat162float(p2[j]) * i2;
        float inv = __fdividef(1.f, s1 + s2 + 1e-6f);
        o1[j] = __float2bfloat16(s1 * inv);
        o2[j] = __float2bfloat16(s2 * inv);
    }
    ((uint4*)g_S)[idx] = *(uint4*)o1;
    ((uint4*)g_S)[4194304 + idx] = *(uint4*)o2;
}

// ---------------- 4) AV: H_ss = A_ss(1024x1024) @ V_{1-ss}(1024x64) ----------------
// grid (8, 64). BM=128, BN=64, BK=32, warp tile 64x32. cp.async A, reg-pipelined V.
__global__ __launch_bounds__(128) void k_av_mma()
{
    __shared__ __nv_bfloat16 As[2][128][40];
    __shared__ __nv_bfloat16 Vs[2][64][40];           // [dim][token]
    const int z = blockIdx.y;
    const int ss = z >> 5, bh = z & 31, b = bh >> 3, h = bh & 7;
    const __nv_bfloat16* Abase = g_S + ((size_t)(ss * 32 + bh) << 20);
    const __nv_bfloat16* Vbase = g_Vh + ((size_t)(b * 2 + (1 - ss)) * 1024) * 512 + h * 64;
    __nv_bfloat16* Cbase = g_attnh + ((size_t)(b * 2 + ss) * 1024) * 512 + h * 64;

    const int tid = threadIdx.x, lane = tid & 31, warp = tid >> 5;
    const int wm = warp >> 1, wn = warp & 1;
    const int g = lane >> 2, t = lane & 3;
    const int m0 = blockIdx.x * 128;
    const int kr = tid >> 2, dseg = (tid & 3) * 16;

    const __nv_bfloat16* srcA0 = Abase + (size_t)(m0 + tid) * 1024;
    const __nv_bfloat16* srcV0 = Vbase + (size_t)kr * 512 + dseg;

    float acc[4][4][4] = {};
    __nv_bfloat16 vr[16];

#define AV_ISSUE_A(K0, BUF)                                           \
    {                                                                 \
        _Pragma("unroll")                                             \
        for (int c = 0; c < 4; c++)                                   \
            cpa16(&As[BUF][tid][c * 8], srcA0 + (K0) + c * 8);        \
    }
#define AV_LD_V(K0)                                                   \
    {                                                                 \
        const __nv_bfloat16* s = srcV0 + (size_t)(K0) * 512;          \
        *(uint4*)vr = *(const uint4*)s;                               \
        *(uint4*)(vr + 8) = *(const uint4*)(s + 8);                   \
    }
#define AV_ST_V(BUF)                                                  \
    {                                                                 \
        _Pragma("unroll")                                             \
        for (int j = 0; j < 16; j++) Vs[BUF][dseg + j][kr] = vr[j];   \
    }

    AV_ISSUE_A(0, 0); CPA_COMMIT;
    AV_LD_V(0); AV_ST_V(0);
    AV_LD_V(32);

    for (int it = 0; it < 32; it++) {
        CPA_WAIT0;
        __syncthreads();
        if (it + 1 < 32) { AV_ISSUE_A((it + 1) * 32, (it + 1) & 1); CPA_COMMIT; }
        const int cb = it & 1;
#pragma unroll
        for (int kk = 0; kk < 32; kk += 16) {
            uint32_t a[4][4];
#pragma unroll
            for (int mi = 0; mi < 4; mi++)
#pragma unroll
                for (int p = 0; p < 4; p++)
                    a[mi][p] = *(const uint32_t*)&As[cb][wm * 64 + mi * 16 + ((p & 1) << 3) + g]
                                                   [kk + 2 * t + ((p >> 1) << 3)];
#pragma unroll
            for (int ni = 0; ni < 4; ni++) {
                uint32_t b0 = *(const uint32_t*)&Vs[cb][wn * 32 + ni * 8 + g][kk + 2 * t];
                uint32_t b1 = *(const uint32_t*)&Vs[cb][wn * 32 + ni * 8 + g][kk + 2 * t + 8];
#pragma unroll
                for (int mi = 0; mi < 4; mi++) mma16816(acc[mi][ni], a[mi], b0, b1);
            }
        }
        if (it + 1 < 32) {
            AV_ST_V((it + 1) & 1);
            if (it + 2 < 32) AV_LD_V((it + 2) * 32);
        }
    }
#undef AV_ISSUE_A
#undef AV_LD_V
#undef AV_ST_V

#pragma unroll
    for (int mi = 0; mi < 4; mi++) {
        int r0 = m0 + wm * 64 + mi * 16 + g;
#pragma unroll
        for (int ni = 0; ni < 4; ni++) {
            int col = wn * 32 + ni * 8 + 2 * t;
            *(uint32_t*)(Cbase + (size_t)r0 * 512 + col)       = pack_bf16x2(acc[mi][ni][0], acc[mi][ni][1]);
            *(uint32_t*)(Cbase + (size_t)(r0 + 8) * 512 + col) = pack_bf16x2(acc[mi][ni][2], acc[mi][ni][3]);
        }
    }
}

// ---------------- 5) output projection: g_proj = attn @ Wo^T + bo ----------------
__global__ __launch_bounds__(128) void k_out_mma(const float* __restrict__ bo)
{
    __shared__ __nv_bfloat16 As[2][128][40];
    __shared__ __nv_bfloat16 Bs[2][128][40];
    const int tid = threadIdx.x, lane = tid & 31, warp = tid >> 5;
    const int wm = warp >> 1, wn = warp & 1;
    const int g = lane >> 2, t = lane & 3;
    const int m0 = blockIdx.y * 128, n0 = blockIdx.x * 128;
    const __nv_bfloat16* Wo = g_Wh + 3ull * 512 * 512;

    const __nv_bfloat16* srcA0 = g_attnh + (size_t)(m0 + tid) * 512;
    const __nv_bfloat16* srcB0 = Wo + (size_t)(n0 + tid) * 512;

    float acc[4][8][4] = {};

#define OUT_ISSUE(K0, BUF)                                            \
    {                                                                 \
        _Pragma("unroll")                                             \
        for (int c = 0; c < 4; c++) {                                 \
            cpa16(&As[BUF][tid][c * 8], srcA0 + (K0) + c * 8);        \
            cpa16(&Bs[BUF][tid][c * 8], srcB0 + (K0) + c * 8);        \
        }                                                             \
    }

    OUT_ISSUE(0, 0); CPA_COMMIT;

    for (int it = 0; it < 16; it++) {
        CPA_WAIT0;
        __syncthreads();
        if (it + 1 < 16) { OUT_ISSUE((it + 1) * 32, (it + 1) & 1); CPA_COMMIT; }
        const int cb = it & 1;
#pragma unroll
        for (int kk = 0; kk < 32; kk += 16) {
            uint32_t a[4][4];
#pragma unroll
            for (int mi = 0; mi < 4; mi++)
#pragma unroll
                for (int p = 0; p < 4; p++)
                    a[mi][p] = *(const uint32_t*)&As[cb][wm * 64 + mi * 16 + ((p & 1) << 3) + g]
                                                   [kk + 2 * t + ((p >> 1) << 3)];
#pragma unroll
            for (int ni = 0; ni < 8; ni++) {
                uint32_t b0 = *(const uint32_t*)&Bs[cb][wn * 64 + ni * 8 + g][kk + 2 * t];
                uint32_t b1 = *(const uint32_t*)&Bs[cb][wn * 64 + ni * 8 + g][kk + 2 * t + 8];
#pragma unroll
                for (int mi = 0; mi < 4; mi++) mma16816(acc[mi][ni], a[mi], b0, b1);
            }
        }
        __syncthreads();
    }
#undef OUT_ISSUE

#pragma unroll
    for (int mi = 0; mi < 4; mi++) {
        int r0 = m0 + wm * 64 + mi * 16 + g;
#pragma unroll
        for (int ni = 0; ni < 8; ni++) {
            int col = n0 + wn * 64 + ni * 8 + 2 * t;
            float b0f = bo[col], b1f = bo[col + 1];
            *(float2*)(g_proj + (size_t)r0 * 512 + col) =
                make_float2(acc[mi][ni][0] + b0f, acc[mi][ni][1] + b1f);
            *(float2*)(g_proj + (size_t)(r0 + 8) * 512 + col) =
                make_float2(acc[mi][ni][2] + b0f, acc[mi][ni][3] + b1f);
        }
    }
}

// ---------------- 6) LayerNorm + gate + residual ----------------
__global__ __launch_bounds__(256) void k_ln(
    const float* __restrict__ hidden,
    const float* __restrict__ ln_g, const float* __restrict__ ln_b,
    const float* __restrict__ alpha, float* __restrict__ out)
{
    const int m = blockIdx.x;
    const int s = (m >> 10) & 1;
    const float* p = g_proj + (size_t)m * 512;
    const int tid = threadIdx.x;
    __shared__ float sm[8];

    float x0 = p[tid], x1 = p[tid + 256];
    float sum = blk_red_sum(x0 + x1, sm);
    float sq  = blk_red_sum(x0 * x0 + x1 * x1, sm);
    float mu  = sum * (1.f / 512.f);
    float var = sq * (1.f / 512.f) - mu * mu;
    float rstd = rsqrtf(var + 1e-5f);
    float al = alpha[s];
    size_t base = (size_t)m * 512;

    {
        int e = tid;
        float y = (x0 - mu) * rstd * ln_g[s * 512 + e] + ln_b[s * 512 + e];
        out[base + e] = hidden[base + e] + y * al;
    }
    {
        int e = tid + 256;
        float y = (x1 - mu) * rstd * ln_g[s * 512 + e] + ln_b[s * 512 + e];
        out[base + e] = hidden[base + e] + y * al;
    }
}

// ---------------- launch ----------------
extern "C" void kernel_launch(void* const* d_in, const int* in_sizes, int n_in,
                              void* d_out, int out_size)
{
    const float* hidden = (const float*)d_in[0];
    const float* Wq = (const float*)d_in[1];  const float* bq = (const float*)d_in[2];
    const float* Wk = (const float*)d_in[3];  const float* bk = (const float*)d_in[4];
    const float* Wv = (const float*)d_in[5];  const float* bv = (const float*)d_in[6];
    const float* Wo = (const float*)d_in[7];  const float* bo = (const float*)d_in[8];
    const float* lng = (const float*)d_in[9]; const float* lnb = (const float*)d_in[10];
    const float* alpha = (const float*)d_in[11];
    float* out = (float*)d_out;

    k_prep<<<5120, 256>>>(hidden, Wq, Wk, Wv, Wo);
    k_qkv_mma<<<dim3(12, 64), 128>>>(bq, bk, bv);
    k_scores_mma<<<dim3(8, 8, 64), 128>>>();
    k_zinv<<<128, 512>>>();
    k_combine2<<<16384, 256>>>();
    k_av_mma<<<dim3(8, 64), 128>>>();
    k_out_mma<<<dim3(4, 64), 128>>>(bo);
    k_ln<<<8192, 256>>>(hidden, lng, lnb, alpha, out);
}